// round 3
// baseline (speedup 1.0000x reference)
#include <cuda_runtime.h>
#include <math.h>

#define BB 48
#define SS 128
#define WW 4
#define KK 256
#define NTHREADS 512
#define NGROUPS 8
#define KP_PER_G (KK / NGROUPS)   // 32

typedef unsigned long long ull;

// Precomputed exp(T * tag_mask), transposed: g_expTt[b][kp][k]
__device__ float g_expTt[BB * KK * KK];

#define FMA2(acc, a, b) \
    asm("fma.rn.f32x2 %0, %1, %2, %0;" : "+l"(acc) : "l"(a), "l"(b))
#define UNPACK2(lo, hi, p) \
    asm("mov.b64 {%0, %1}, %2;" : "=f"(lo), "=f"(hi) : "l"(p))

// ---------------------------------------------------------------------------
// Prep: expTt[b][kp][k] = exp(T[b][k][kp] * tag_mask[b][k][kp])
// ---------------------------------------------------------------------------
__global__ __launch_bounds__(256) void prep_kernel(const float* __restrict__ T,
                                                   const float* __restrict__ tagm) {
    __shared__ float tile[32][33];
    const int b   = blockIdx.z;
    const int kp0 = blockIdx.x * 32;
    const int k0  = blockIdx.y * 32;
    const int x = threadIdx.x;
    const int y = threadIdx.y;
    const size_t base = (size_t)b * KK * KK;

    #pragma unroll
    for (int i = y; i < 32; i += 8) {
        size_t idx = base + (size_t)(k0 + i) * KK + (kp0 + x);
        tile[i][x] = __expf(T[idx] * tagm[idx]);
    }
    __syncthreads();
    #pragma unroll
    for (int i = y; i < 32; i += 8) {
        g_expTt[base + (size_t)(kp0 + i) * KK + (k0 + x)] = tile[x][i];
    }
}

// ---------------------------------------------------------------------------
// Main: one block per batch. 512 threads: 8 groups x 64 threads for the
// K x K x W exp-domain mat-vec (f32x2 packed FFMA), 256 threads (=k) for
// the per-label logsumexp bookkeeping.
// ---------------------------------------------------------------------------
__global__ __launch_bounds__(NTHREADS) void crf_kernel(
    const float* __restrict__ logits,
    const float* __restrict__ hc,
    const float* __restrict__ tagm,
    const int*   __restrict__ textmask,
    float* __restrict__ out)
{
    __shared__ float4 sVd[KK][2];           // [(v0,v0,v1,v1),(v2,v2,v3,v3)] per kp
    __shared__ float4 sPart[NGROUPS][KK];   // partial dot per group, (w0..w3)
    __shared__ float  sred[16];

    const int tid  = threadIdx.x;
    const int b    = blockIdx.x;
    const int lane = tid & 31;
    const int wid  = tid >> 5;
    const int g    = tid >> 6;      // group 0..7
    const int u    = tid & 63;      // column quad within group

    // ---- length[b] ----
    int t = (tid < SS) ? textmask[b * SS + tid] : 0;
    #pragma unroll
    for (int o = 16; o; o >>= 1) t += __shfl_xor_sync(0xffffffffu, t, o);
    if (lane == 0) sred[wid] = (float)t;
    __syncthreads();
    int L = 0;
    #pragma unroll
    for (int i = 0; i < 16; i++) L += (int)sred[i];
    __syncthreads();
    if (L == 0) { if (tid == 0) out[b] = logf(256.0f); return; }
    const int JMAX = (L < SS) ? L : SS;

    const ulonglong2* __restrict__ Tt2 =
        (const ulonglong2*)(g_expTt + (size_t)b * KK * KK);  // 64 u2 per kp row
    const ulonglong2* __restrict__ tbase = Tt2 + (size_t)(g * KP_PER_G) * 64 + u;
    const ulonglong2* __restrict__ svd2 = (const ulonglong2*)&sVd[0][0];

    const int k = tid;  // label index, valid when tid < KK
    float tm0 = 0.0f;
    float eb0 = 0.f, eb1 = 0.f, eb2 = 0.f, eb3 = 0.f;   // emissions for step j
    float h0, h1, h2, h3;                               // alpha history (regs)
    float m0, m1, m2, m3;                               // rowmax history (regs)
    h0 = h1 = h2 = h3 = 0.f; m0 = m1 = m2 = m3 = 0.f;

    if (tid < KK) {
        tm0 = tagm[(size_t)b * KK * KK + k];
        const size_t e0i = ((size_t)b * SS) * WW * KK + k;
        eb0 = (logits[e0i          ] + hc[e0i          ]) * tm0;
        eb1 = (logits[e0i + 1 * KK ] + hc[e0i + 1 * KK ]) * tm0;
        eb2 = (logits[e0i + 2 * KK ] + hc[e0i + 2 * KK ]) * tm0;
        eb3 = (logits[e0i + 3 * KK ] + hc[e0i + 3 * KK ]) * tm0;
    }

    for (int j = 0; j < JMAX; j++) {
        const int nT = (j < WW) ? j : WW;

        // ---- phase A: build v rows, history maxes ----
        float M = (j < WW) ? 0.0f : -1e30f;
        if (tid < KK) {
            float v0 = 0.f, v1 = 0.f, v2 = 0.f, v3 = 0.f;
            if (nT > 0) { v0 = __expf(h0 - m0); M = fmaxf(M, m0); }
            if (nT > 1) { v1 = __expf(h1 - m1); M = fmaxf(M, m1); }
            if (nT > 2) { v2 = __expf(h2 - m2); M = fmaxf(M, m2); }
            if (nT > 3) { v3 = __expf(h3 - m3); M = fmaxf(M, m3); }
            sVd[k][0] = make_float4(v0, v0, v1, v1);
            sVd[k][1] = make_float4(v2, v2, v3, v3);
        }
        __syncthreads();

        // ---- prefetch next step's emissions (hidden under the mat-vec) ----
        float lb0 = 0.f, lb1 = 0.f, lb2 = 0.f, lb3 = 0.f;
        float hb0 = 0.f, hb1 = 0.f, hb2 = 0.f, hb3 = 0.f;
        if (tid < KK && (j + 1) < JMAX) {
            const size_t ei = (((size_t)b * SS + (j + 1)) * WW) * KK + k;
            lb0 = logits[ei];          hb0 = hc[ei];
            lb1 = logits[ei + 1 * KK]; hb1 = hc[ei + 1 * KK];
            lb2 = logits[ei + 2 * KK]; hb2 = hc[ei + 2 * KK];
            lb3 = logits[ei + 3 * KK]; hb3 = hc[ei + 3 * KK];
        }

        // ---- phase B: packed-f32x2 mat-vec over my kp slice ----
        ull a00 = 0, a01 = 0, a02 = 0, a03 = 0;   // k-pair (4u, 4u+1), w=0..3
        ull a10 = 0, a11 = 0, a12 = 0, a13 = 0;   // k-pair (4u+2, 4u+3)
        const int kp0 = g * KP_PER_G;
        #pragma unroll 8
        for (int i = 0; i < KP_PER_G; i++) {
            ulonglong2 tv  = __ldg(tbase + (size_t)i * 64);
            ulonglong2 vd0 = svd2[(kp0 + i) * 2 + 0];
            ulonglong2 vd1 = svd2[(kp0 + i) * 2 + 1];
            FMA2(a00, tv.x, vd0.x);  FMA2(a10, tv.y, vd0.x);
            FMA2(a01, tv.x, vd0.y);  FMA2(a11, tv.y, vd0.y);
            FMA2(a02, tv.x, vd1.x);  FMA2(a12, tv.y, vd1.x);
            FMA2(a03, tv.x, vd1.y);  FMA2(a13, tv.y, vd1.y);
        }
        // unpack and write partials
        {
            float f00, f10, f20, f30, f01, f11, f21, f31;
            float f02, f12, f22, f32, f03, f13, f23, f33;
            UNPACK2(f00, f10, a00);  UNPACK2(f20, f30, a10);
            UNPACK2(f01, f11, a01);  UNPACK2(f21, f31, a11);
            UNPACK2(f02, f12, a02);  UNPACK2(f22, f32, a12);
            UNPACK2(f03, f13, a03);  UNPACK2(f23, f33, a13);
            sPart[g][4 * u + 0] = make_float4(f00, f01, f02, f03);
            sPart[g][4 * u + 1] = make_float4(f10, f11, f12, f13);
            sPart[g][4 * u + 2] = make_float4(f20, f21, f22, f23);
            sPart[g][4 * u + 3] = make_float4(f30, f31, f32, f33);
        }
        __syncthreads();

        // ---- phase C1: combine, compute alpha, start rowmax reduce ----
        float a = 0.f;
        if (tid < KK) {
            float4 s = sPart[0][k];
            float aw0 = s.x, aw1 = s.y, aw2 = s.z, aw3 = s.w;
            #pragma unroll
            for (int gg = 1; gg < NGROUPS; gg++) {
                float4 p = sPart[gg][k];
                aw0 += p.x; aw1 += p.y; aw2 += p.z; aw3 += p.w;
            }
            float tot = 0.0f;
            if (nT > 0) tot += __expf(eb0 + m0 - M) * aw0;
            if (nT > 1) tot += __expf(eb1 + m1 - M) * aw1;
            if (nT > 2) tot += __expf(eb2 + m2 - M) * aw2;
            if (nT > 3) tot += __expf(eb3 + m3 - M) * aw3;
            if (j < WW) {   // initial-state (zero) row at w == j
                float einit = (j == 0) ? eb0 : (j == 1) ? eb1 : (j == 2) ? eb2 : eb3;
                tot += 256.0f * __expf(einit - M);
            }
            a = M + __logf(tot);

            float mv = a;
            #pragma unroll
            for (int o = 16; o; o >>= 1)
                mv = fmaxf(mv, __shfl_xor_sync(0xffffffffu, mv, o));
            if (lane == 0) sred[wid] = mv;
        }
        __syncthreads();

        // ---- phase C2: finish rowmax, shift history, roll emissions ----
        if (tid < KK) {
            float rowmax = sred[0];
            #pragma unroll
            for (int i = 1; i < 8; i++) rowmax = fmaxf(rowmax, sred[i]);
            m3 = m2; m2 = m1; m1 = m0; m0 = rowmax;
            h3 = h2; h2 = h1; h1 = h0; h0 = a;
            eb0 = (lb0 + hb0) * tm0;
            eb1 = (lb1 + hb1) * tm0;
            eb2 = (lb2 + hb2) * tm0;
            eb3 = (lb3 + hb3) * tm0;
            if (j + 1 == JMAX) {        // final logsumexp over k
                float sv = __expf(a - rowmax);
                #pragma unroll
                for (int o = 16; o; o >>= 1)
                    sv += __shfl_xor_sync(0xffffffffu, sv, o);
                if (lane == 0) sred[8 + wid] = sv;
            }
        }
        __syncthreads();
    }

    if (tid == 0) {
        float rowmax = sred[0];
        #pragma unroll
        for (int i = 1; i < 8; i++) rowmax = fmaxf(rowmax, sred[i]);
        float ssum = 0.f;
        #pragma unroll
        for (int i = 0; i < 8; i++) ssum += sred[8 + i];
        out[b] = rowmax + __logf(ssum);
    }
}

// ---------------------------------------------------------------------------
extern "C" void kernel_launch(void* const* d_in, const int* in_sizes, int n_in,
                              void* d_out, int out_size) {
    const float* logits = (const float*)d_in[0];   // (B,S,W,K) f32
    const float* T      = (const float*)d_in[1];   // (B,K,K)   f32
    const float* hc     = (const float*)d_in[2];   // (B,S,W,K) f32
    const float* tagm   = (const float*)d_in[3];   // (B,K,K)   f32
    const int*   tmask  = (const int*)  d_in[4];   // (B,S)     i32
    float* out = (float*)d_out;                    // (1,B)     f32

    dim3 pb(32, 8);
    dim3 pg(KK / 32, KK / 32, BB);
    prep_kernel<<<pg, pb>>>(T, tagm);
    crf_kernel<<<BB, NTHREADS>>>(logits, hc, tagm, tmask, out);
}

// round 5
// speedup vs baseline: 1.7581x; 1.7581x over previous
#include <cuda_runtime.h>
#include <cstdint>
#include <math.h>

#define BB 48
#define SS 128
#define WW 4
#define KK 256
#define KH 128        // k rows per CTA (half)
#define NT 512

typedef unsigned long long ull;

#define FMA2(acc, a, b) \
    asm("fma.rn.f32x2 %0, %1, %2, %0;" : "+l"(acc) : "l"(a), "l"(b))
#define UNPACK2(lo, hi, p) \
    asm("mov.b64 {%0, %1}, %2;" : "=f"(lo), "=f"(hi) : "l"(p))
#define DUP2(d, f) \
    asm("mov.b64 %0, {%1, %1};" : "=l"(d) : "f"(f))

static __device__ __forceinline__ uint32_t s2u(const void* p) {
    uint32_t a;
    asm("{ .reg .u64 t; cvta.to.shared.u64 t, %1; cvt.u32.u64 %0, t; }"
        : "=r"(a) : "l"(p));
    return a;
}
static __device__ __forceinline__ uint32_t mapa_u(uint32_t a, int rk) {
    uint32_t r;
    asm("mapa.shared::cluster.u32 %0, %1, %2;" : "=r"(r) : "r"(a), "r"(rk));
    return r;
}
static __device__ __forceinline__ void mbar_init(uint32_t mb, uint32_t cnt) {
    asm volatile("mbarrier.init.shared.b64 [%0], %1;" :: "r"(mb), "r"(cnt) : "memory");
}
static __device__ __forceinline__ void arrive_remote(uint32_t mb) {
    asm volatile("mbarrier.arrive.release.cluster.shared::cluster.b64 _, [%0];"
                 :: "r"(mb) : "memory");
}
static __device__ __forceinline__ void wait_parity(uint32_t mb, uint32_t par) {
    asm volatile(
        "{\n\t.reg .pred P;\n\t"
        "W_%=:\n\t"
        "mbarrier.try_wait.parity.acquire.cluster.shared::cta.b64 P, [%0], %1, 0x989680;\n\t"
        "@!P bra W_%=;\n\t}"
        :: "r"(mb), "r"(par) : "memory");
}
static __device__ __forceinline__ void st_cluster_v4(uint32_t a, float4 v) {
    asm volatile("st.shared::cluster.v4.f32 [%0], {%1,%2,%3,%4};"
                 :: "r"(a), "f"(v.x), "f"(v.y), "f"(v.z), "f"(v.w) : "memory");
}
static __device__ __forceinline__ void st_cluster_f32(uint32_t a, float v) {
    asm volatile("st.shared::cluster.f32 [%0], %1;" :: "r"(a), "f"(v) : "memory");
}

extern "C" __global__ void __launch_bounds__(NT, 1) __cluster_dims__(2, 1, 1)
crf_cluster_kernel(const float* __restrict__ logits,
                   const float* __restrict__ T,
                   const float* __restrict__ hc,
                   const float* __restrict__ tagm,
                   const int*   __restrict__ textmask,
                   float* __restrict__ out)
{
    __shared__ float4 sVd[KK];        // (v0,v1,v2,v3) per kp
    __shared__ float4 sPart[8][KH];   // per-kp-slice partial dots
    __shared__ float  sRing[8][KK];   // alpha history ring (full rows)
    __shared__ float  sRmax[8];       // peer half-max per slot
    __shared__ float  sRed[16];
    __shared__ ull    sMbar[8];

    const int tid  = threadIdx.x;
    const int lane = tid & 31;
    const int wid  = tid >> 5;
    const int b    = blockIdx.x >> 1;
    const int r    = blockIdx.x & 1;
    const int s    = tid >> 6;        // kp slice 0..7 (32 kp each)
    const int p    = tid & 63;        // k-pair within my half

    // ---- length[b] ----
    {
        int t = (tid < SS) ? textmask[b * SS + tid] : 0;
        #pragma unroll
        for (int o = 16; o; o >>= 1) t += __shfl_xor_sync(0xffffffffu, t, o);
        if (lane == 0) sRed[wid] = (float)t;
    }
    __syncthreads();
    int L = 0;
    #pragma unroll
    for (int i = 0; i < 16; i++) L += (int)sRed[i];
    __syncthreads();
    if (L == 0) { if (r == 0 && tid == 0) out[b] = logf(256.0f); return; }
    const int JMAX = (L < SS) ? L : SS;

    // ---- mbarriers + cluster handshake ----
    if (tid < 8) mbar_init(s2u(&sMbar[tid]), 32);
    __syncthreads();
    asm volatile("barrier.cluster.arrive.aligned;" ::: "memory");
    asm volatile("barrier.cluster.wait.aligned;"   ::: "memory");

    const uint32_t myRing  = s2u(sRing);
    const uint32_t myMbar  = s2u(sMbar);
    const int      peer    = 1 - r;
    const uint32_t peerRing = mapa_u(myRing, peer);
    const uint32_t peerRmax = mapa_u(s2u(sRmax), peer);
    const uint32_t peerMbar = mapa_u(myMbar, peer);

    // ---- T slice into registers: Treg[i] = expT[k0][kp0+i], Treg[32+i] = expT[k1][..] ----
    float Treg[64];
    {
        const size_t rb = ((size_t)b * KK + (size_t)(r * KH)) * KK;
        const int k0 = 2 * p, k1 = 2 * p + 1, kp0 = 32 * s;
        const float4* Ta = (const float4*)(T    + rb + (size_t)k0 * KK + kp0);
        const float4* Ma = (const float4*)(tagm + rb + (size_t)k0 * KK + kp0);
        const float4* Tb = (const float4*)(T    + rb + (size_t)k1 * KK + kp0);
        const float4* Mb = (const float4*)(tagm + rb + (size_t)k1 * KK + kp0);
        #pragma unroll
        for (int q = 0; q < 8; q++) {
            float4 tv = __ldg(Ta + q), mv = __ldg(Ma + q);
            Treg[4 * q + 0] = __expf(tv.x * mv.x);
            Treg[4 * q + 1] = __expf(tv.y * mv.y);
            Treg[4 * q + 2] = __expf(tv.z * mv.z);
            Treg[4 * q + 3] = __expf(tv.w * mv.w);
            float4 tw = __ldg(Tb + q), mw = __ldg(Mb + q);
            Treg[32 + 4 * q + 0] = __expf(tw.x * mw.x);
            Treg[32 + 4 * q + 1] = __expf(tw.y * mw.y);
            Treg[32 + 4 * q + 2] = __expf(tw.z * mw.z);
            Treg[32 + 4 * q + 3] = __expf(tw.w * mw.w);
        }
    }

    // ---- emissions for my k (tid<128): k_global = r*KH + tid ----
    const int kg = r * KH + tid;
    float tm0 = 0.f, e0 = 0.f, e1 = 0.f, e2 = 0.f, e3 = 0.f;
    if (tid < KH) {
        tm0 = tagm[(size_t)b * KK * KK + kg];
        const size_t ei = ((size_t)b * SS) * WW * KK + kg;
        e0 = (logits[ei         ] + hc[ei         ]) * tm0;
        e1 = (logits[ei + 1 * KK] + hc[ei + 1 * KK]) * tm0;
        e2 = (logits[ei + 2 * KK] + hc[ei + 2 * KK]) * tm0;
        e3 = (logits[ei + 3 * KK] + hc[ei + 3 * KK]) * tm0;
    }

    float m0 = 0.f, m1 = 0.f, m2 = 0.f, m3 = 0.f;   // global rowmax history

    for (int j = 0; j < JMAX; j++) {
        const int nT = (j < WW) ? j : WW;

        // ---- phase A: M and v rows ----
        float M = (j < WW) ? 0.0f : -1e30f;
        if (nT > 0) M = fmaxf(M, m0);
        if (nT > 1) M = fmaxf(M, m1);
        if (nT > 2) M = fmaxf(M, m2);
        if (nT > 3) M = fmaxf(M, m3);
        if (tid < KK) {
            float v0 = 0.f, v1 = 0.f, v2 = 0.f, v3 = 0.f;
            if (nT > 0) v0 = __expf(sRing[(j - 1) & 7][tid] - m0);
            if (nT > 1) v1 = __expf(sRing[(j - 2) & 7][tid] - m1);
            if (nT > 2) v2 = __expf(sRing[(j - 3) & 7][tid] - m2);
            if (nT > 3) v3 = __expf(sRing[(j - 4) & 7][tid] - m3);
            sVd[tid] = make_float4(v0, v1, v2, v3);
        }
        __syncthreads();

        // ---- prefetch next emissions (hidden under mat-vec) ----
        float l0 = 0.f, l1 = 0.f, l2 = 0.f, l3 = 0.f;
        float q0 = 0.f, q1 = 0.f, q2 = 0.f, q3 = 0.f;
        if (tid < KH && (j + 1) < JMAX) {
            const size_t ei = (((size_t)b * SS + (j + 1)) * WW) * KK + kg;
            l0 = logits[ei];          q0 = hc[ei];
            l1 = logits[ei + 1 * KK]; q1 = hc[ei + 1 * KK];
            l2 = logits[ei + 2 * KK]; q2 = hc[ei + 2 * KK];
            l3 = logits[ei + 3 * KK]; q3 = hc[ei + 3 * KK];
        }

        // ---- phase B: register-resident mat-vec (w-packed FFMA2) ----
        ull a01_0 = 0, a23_0 = 0, a01_1 = 0, a23_1 = 0;
        {
            const ulonglong2* vb = (const ulonglong2*)&sVd[s << 5];
            #pragma unroll
            for (int i = 0; i < 32; i++) {
                ulonglong2 vd = vb[i];               // broadcast LDS.128
                ull t0d, t1d;
                DUP2(t0d, Treg[i]);
                DUP2(t1d, Treg[32 + i]);
                FMA2(a01_0, t0d, vd.x);  FMA2(a23_0, t0d, vd.y);
                FMA2(a01_1, t1d, vd.x);  FMA2(a23_1, t1d, vd.y);
            }
        }
        {
            float f0, f1, f2, f3;
            UNPACK2(f0, f1, a01_0); UNPACK2(f2, f3, a23_0);
            sPart[s][2 * p]     = make_float4(f0, f1, f2, f3);
            UNPACK2(f0, f1, a01_1); UNPACK2(f2, f3, a23_1);
            sPart[s][2 * p + 1] = make_float4(f0, f1, f2, f3);
        }
        __syncthreads();

        // ---- phase C: combine slices, alpha, local half-max ----
        float aN = 0.f;
        if (tid < KH) {
            float4 aw = sPart[0][tid];
            #pragma unroll
            for (int ss2 = 1; ss2 < 8; ss2++) {
                float4 t4 = sPart[ss2][tid];
                aw.x += t4.x; aw.y += t4.y; aw.z += t4.z; aw.w += t4.w;
            }
            float tot = 0.0f;
            if (nT > 0) tot += __expf(e0 + m0 - M) * aw.x;
            if (nT > 1) tot += __expf(e1 + m1 - M) * aw.y;
            if (nT > 2) tot += __expf(e2 + m2 - M) * aw.z;
            if (nT > 3) tot += __expf(e3 + m3 - M) * aw.w;
            if (j < WW) {   // initial-state (zeros) row at w == j
                float ein = (j == 0) ? e0 : (j == 1) ? e1 : (j == 2) ? e2 : e3;
                tot += 256.0f * __expf(ein - M);
            }
            aN = M + __logf(tot);
            sRing[j & 7][r * KH + tid] = aN;
            float mv = aN;
            #pragma unroll
            for (int o = 16; o; o >>= 1)
                mv = fmaxf(mv, __shfl_xor_sync(0xffffffffu, mv, o));
            if (lane == 0) sRed[wid] = mv;       // wid 0..3
        }
        __syncthreads();
        const float halfmax = fmaxf(fmaxf(sRed[0], sRed[1]), fmaxf(sRed[2], sRed[3]));

        // ---- push my alpha half + halfmax to peer (warp 8) ----
        if (wid == 8) {
            const uint32_t off = ((uint32_t)(j & 7) * KK + (uint32_t)(r * KH) + lane * 4) * 4;
            float4 av = *(const float4*)&sRing[j & 7][r * KH + lane * 4];
            st_cluster_v4(peerRing + off, av);
            if (lane == 0)
                st_cluster_f32(peerRmax + (uint32_t)(j & 7) * 4, halfmax);
            arrive_remote(peerMbar + (uint32_t)(j & 7) * 8);
        }

        // ---- wait for peer's half, finish step ----
        wait_parity(myMbar + (uint32_t)(j & 7) * 8, (uint32_t)((j >> 3) & 1));
        const float rowmax = fmaxf(halfmax, sRmax[j & 7]);

        m3 = m2; m2 = m1; m1 = m0; m0 = rowmax;
        e0 = (l0 + q0) * tm0;  e1 = (l1 + q1) * tm0;
        e2 = (l2 + q2) * tm0;  e3 = (l3 + q3) * tm0;

        if (j + 1 == JMAX) {     // final logsumexp over full alpha row
            if (tid < KK) {
                float sv = __expf(sRing[j & 7][tid] - rowmax);
                #pragma unroll
                for (int o = 16; o; o >>= 1)
                    sv += __shfl_xor_sync(0xffffffffu, sv, o);
                if (lane == 0) sRed[8 + wid] = sv;   // wid 0..7
            }
            __syncthreads();
            if (r == 0 && tid == 0) {
                float ssum = 0.f;
                #pragma unroll
                for (int i = 0; i < 8; i++) ssum += sRed[8 + i];
                out[b] = rowmax + __logf(ssum);
            }
        }
    }

    // no CTA exits while peer stores may be in flight (last arrivals consumed above)
    asm volatile("barrier.cluster.arrive.aligned;" ::: "memory");
    asm volatile("barrier.cluster.wait.aligned;"   ::: "memory");
}

// ---------------------------------------------------------------------------
extern "C" void kernel_launch(void* const* d_in, const int* in_sizes, int n_in,
                              void* d_out, int out_size) {
    const float* logits = (const float*)d_in[0];   // (B,S,W,K) f32
    const float* T      = (const float*)d_in[1];   // (B,K,K)   f32
    const float* hc     = (const float*)d_in[2];   // (B,S,W,K) f32
    const float* tagm   = (const float*)d_in[3];   // (B,K,K)   f32
    const int*   tmask  = (const int*)  d_in[4];   // (B,S)     i32
    float* out = (float*)d_out;                    // (1,B)     f32

    crf_cluster_kernel<<<BB * 2, NT>>>(logits, T, hc, tagm, tmask, out);
}